// round 15
// baseline (speedup 1.0000x reference)
#include <cuda_runtime.h>
#include <cstdint>

// ============================================================================
// Inverse NTT over F_P, P = 2013265921, N = 2^22, C = 4. Four-step 2048x2048.
// R15 = R14 + (a) pass-A input load lane remap: 4 lanes cover one 64B chunk
// (2 columns x 32B point) -> 8 lines/warp access instead of 16 (wavefront
// halving), (b) prep folded into the passes (each CTA builds its smem twiddle
// tables from the global input; 2 launches total).
// ============================================================================

static constexpr uint32_t MOD    = 2013265921u;
static constexpr uint32_t N_FULL = 1u << 22;
static constexpr uint32_t N_HALF = 1u << 21;

static constexpr uint32_t calc_pinv() {
    uint32_t x = MOD;
    for (int i = 0; i < 5; ++i) x *= 2u - MOD * x;
    return x;
}
static constexpr uint32_t PINV_NEG = (uint32_t)(0u - calc_pinv());

static constexpr uint32_t calc_r2() {     // 2^64 mod P
    unsigned long long r = 1;
    for (int i = 0; i < 64; ++i) { r <<= 1; if (r >= MOD) r -= MOD; }
    return (uint32_t)r;
}
static constexpr uint32_t R2 = calc_r2();

#define DT_I32 0
#define DT_I64 1
#define DT_F32 2
#define DT_F64 3

static constexpr int COLPAD = 2305;       // padded uint4 stride per column
static constexpr int SMEM_A_BYTES = 2 * COLPAD * 16 + 3 * 2048 * 4;  // 98336
static constexpr int SMEM_B_BYTES = 2 * COLPAD * 16 + 2048 * 4;      // 81952

#define OFFH(H) (2048 - 2 * (H))          // stage-table base

__device__ uint4 g_buf[N_FULL];           // 64 MB intermediate

// Named barrier: 256 threads of group (id-1). Per-CTA resource.
#define NB(id) asm volatile("bar.sync %0, 256;" :: "r"(id) : "memory")

// ---------------- modular primitives (branch-free) ----------------
__device__ __forceinline__ uint32_t mmul(uint32_t a, uint32_t b) {
    // a < P (twiddle), b < 2P allowed: r < 1.938P, single min -> [0,P).
    unsigned long long t = (unsigned long long)a * b;
    uint32_t m = (uint32_t)t * PINV_NEG;
    uint32_t r = (uint32_t)((t + (unsigned long long)m * MOD) >> 32);
    return min(r, r - MOD);
}
__device__ __forceinline__ uint32_t addm(uint32_t a, uint32_t b) {
    uint32_t s = a + b; return min(s, s - MOD);
}
__device__ __forceinline__ uint32_t subm(uint32_t a, uint32_t b) {
    uint32_t d = a - b; return min(d, d + MOD);
}
__device__ __forceinline__ uint32_t subl(uint32_t a, uint32_t b) {
    return a - b + MOD;                   // lazy: < 2P, only feeds mmul
}

__device__ __forceinline__ void bfly(uint4& lo, uint4& hi, uint32_t tw) {
    uint32_t a, d;
    a = addm(lo.x, hi.x); d = subl(lo.x, hi.x); lo.x = a; hi.x = mmul(tw, d);
    a = addm(lo.y, hi.y); d = subl(lo.y, hi.y); lo.y = a; hi.y = mmul(tw, d);
    a = addm(lo.z, hi.z); d = subl(lo.z, hi.z); lo.z = a; hi.z = mmul(tw, d);
    a = addm(lo.w, hi.w); d = subl(lo.w, hi.w); lo.w = a; hi.w = mmul(tw, d);
}
__device__ __forceinline__ void bfly1(uint4& lo, uint4& hi) {   // twiddle == 1
    uint32_t a, d;
    a = addm(lo.x, hi.x); d = subm(lo.x, hi.x); lo.x = a; hi.x = d;
    a = addm(lo.y, hi.y); d = subm(lo.y, hi.y); lo.y = a; hi.y = d;
    a = addm(lo.z, hi.z); d = subm(lo.z, hi.z); lo.z = a; hi.z = d;
    a = addm(lo.w, hi.w); d = subm(lo.w, hi.w); lo.w = a; hi.w = d;
}
__device__ __forceinline__ void scale4(uint4& v, uint32_t tw) {
    v.x = mmul(tw, v.x); v.y = mmul(tw, v.y);
    v.z = mmul(tw, v.z); v.w = mmul(tw, v.w);
}

// Three consecutive DIF stages (halves 4S, 2S, S) with the stage-indexed
// table: twiddle for half H at lo-position p is ts[OFFH(H) + (p mod H)].
template <int S>
__device__ __forceinline__ void dif_group(uint4 x[8], int base,
                                          const uint32_t* ts) {
#pragma unroll
    for (int j = 0; j < 4; ++j) {                       // half = 4S
        int p = base + j * S;
        bfly(x[j], x[j + 4], ts[OFFH(4 * S) + (p & (4 * S - 1))]);
    }
#pragma unroll
    for (int k = 0; k < 4; ++k) {                       // half = 2S
        int j = (k & 1) + ((k & 2) << 1);
        int p = base + j * S;
        bfly(x[j], x[j + 2], ts[OFFH(2 * S) + (p & (2 * S - 1))]);
    }
#pragma unroll
    for (int j = 0; j < 8; j += 2) {                    // half = S
        int p = base + j * S;
        bfly(x[j], x[j + 1], ts[OFFH(S) + (p & (S - 1))]);
    }
}

__device__ __forceinline__ int padi(int i) { return i + (i >> 3); }

// In-place size-2048 DIF (validated choreography). Entry: x[j] = point
// (t+256j). Exit: x[j] = storage slot (8t+j); slot r holds output brev11(r).
__device__ __forceinline__ void dif2048(uint4 x[8], int t, uint4* sm,
                                        const uint32_t* ts, int bid) {
    dif_group<256>(x, t, ts);                           // halves 1024,512,256
#pragma unroll
    for (int j = 0; j < 8; ++j) sm[padi(t + 256 * j)] = x[j];
    NB(bid);
    int b1 = ((t >> 5) << 8) | (t & 31);
#pragma unroll
    for (int j = 0; j < 8; ++j) x[j] = sm[padi(b1 + 32 * j)];
    dif_group<32>(x, b1, ts);                           // halves 128,64,32
    NB(bid);
#pragma unroll
    for (int j = 0; j < 8; ++j) sm[padi(b1 + 32 * j)] = x[j];
    NB(bid);
    int b2 = ((t >> 2) << 5) | (t & 3);
#pragma unroll
    for (int j = 0; j < 8; ++j) x[j] = sm[padi(b2 + 4 * j)];
    dif_group<4>(x, b2, ts);                            // halves 16,8,4
    NB(bid);
#pragma unroll
    for (int j = 0; j < 8; ++j) sm[padi(b2 + 4 * j)] = x[j];
    NB(bid);
#pragma unroll
    for (int j = 0; j < 8; ++j) x[j] = sm[padi(8 * t + j)];
    uint32_t w512 = ts[OFFH(2) + 1];                    // = tw[2^20]R; halves 2,1
    bfly1(x[0], x[2]); bfly(x[1], x[3], w512);
    bfly1(x[4], x[6]); bfly(x[5], x[7], w512);
    bfly1(x[0], x[1]); bfly1(x[2], x[3]);
    bfly1(x[4], x[5]); bfly1(x[6], x[7]);
}

// dtype probe (tw[0] == 1 in every encoding):
//   int64: w0=1,w1=0   int32: w0=1,w1!=0   f64: w0=0   f32: w0=0x3F800000
__device__ __forceinline__ int probe_dtype(const void* tw) {
    const uint32_t* w = (const uint32_t*)tw;
    if (w[0] == 1u) return (w[1] == 0u) ? DT_I64 : DT_I32;
    if (w[0] == 0u) return DT_F64;
    return DT_F32;
}
__device__ __forceinline__ uint32_t load_elem(const void* p, size_t i, int dt) {
    switch (dt) {
        case DT_I64: return (uint32_t)((const unsigned long long*)p)[i];
        case DT_F64: return (uint32_t)__double2ll_rn(((const double*)p)[i]);
        case DT_F32: return (uint32_t)__float2ll_rn(((const float*)p)[i]);
        default:     return ((const uint32_t*)p)[i];
    }
}

// Build the stage-indexed butterfly table in smem (2046 entries) from the
// global twiddle input. Tst[OFFH(H)+i] = tw[(i*1024/H)<<11] * R (Montgomery).
__device__ __forceinline__ void build_tst(uint32_t* sTst, const void* tw,
                                          int dt, int t, int nthr) {
    for (int E = t; E < 2046; E += nthr) {
        unsigned u = 2048u - (unsigned)E;               // u in (H, 2H]
        int lg = 31 - __clz(u - 1);                     // log2 H
        int i  = (2 << lg) - (int)u;                    // i < H
        sTst[E] = mmul(load_elem(tw, (size_t)i << (21 - lg), dt), R2);
    }
}

// ---------------- pass A: 2 columns per CTA (2 CTAs/SM) ----------------
__global__ void __launch_bounds__(512, 2) ntt_pass_a(const void* __restrict__ in,
                                                     const void* __restrict__ tw,
                                                     const void* __restrict__ ninv) {
    extern __shared__ uint4 smem_raw[];
    uint4*    sdata = smem_raw;                         // 2 x COLPAD
    uint32_t* sTst  = (uint32_t*)(smem_raw + 2 * COLPAD);   // 2048
    uint32_t* sT1   = sTst + 2048;                      // 2048 (full, scale)
    uint32_t* sT2   = sT1 + 2048;                       // 2048 (scale)
    int t  = threadIdx.x;
    int c0 = blockIdx.x * 2;
    int dt = probe_dtype(tw);

    // Build tables in smem directly from global twiddle input (L2-hot).
    {
        uint32_t nm = mmul(load_elem(ninv, 0, dt), R2); // n_inv * R
        for (int i = t; i < 1024; i += 512) {
            uint32_t v = mmul(load_elem(tw, (size_t)i << 11, dt), R2);
            sT1[i] = v; sT1[i + 1024] = MOD - v;        // omega^-{2^21} = -1
        }
        for (int i = t; i < 2048; i += 512)
            sT2[i] = mmul(mmul(load_elem(tw, i, dt), R2), nm);
        build_tst(sTst, tw, dt, t, 512);
    }

    // Load phase. int64/f64: lanes (q = 16B chunk-of-64B, rows) -> every
    // warp access covers 8 full 64B chunks = 8 lines (64B/wavefront).
    if (dt == DT_I64 || dt == DT_F64) {
        int q  = t & 3;                                 // 16B chunk in 64B row-pair
        int c  = q >> 1;                                // column
        int h  = q & 1;                                 // uint4 half (.xy/.zw)
        int tp = t >> 2;                                // 128 row slots
        const char* base = (const char*)in;
#pragma unroll
        for (int it = 0; it < 16; ++it) {
            int p = it * 128 + tp;
            const char* chunk = base + ((size_t)p * 2048 + c0) * 32 + q * 16;
            uint2 w;
            if (dt == DT_I64) {
                ulonglong2 v = __ldcs((const ulonglong2*)chunk);
                w = make_uint2((uint32_t)v.x, (uint32_t)v.y);
            } else {
                double2 v = __ldcs((const double2*)chunk);
                w = make_uint2((uint32_t)__double2ll_rn(v.x),
                               (uint32_t)__double2ll_rn(v.y));
            }
            *((uint2*)(sdata + c * COLPAD + padi(p)) + h) = w;
        }
    } else {                                            // 16B/point dtypes
        int c = t & 1;
        int tp = t >> 1;
        if (dt == DT_I32) {
#pragma unroll
            for (int it = 0; it < 8; ++it) {
                int p = it * 256 + tp;
                sdata[c * COLPAD + padi(p)] =
                    __ldcs((const uint4*)in + (size_t)p * 2048 + c0 + c);
            }
        } else {                                        // DT_F32
#pragma unroll
            for (int it = 0; it < 8; ++it) {
                int p = it * 256 + tp;
                float4 f = __ldcs((const float4*)in + (size_t)p * 2048 + c0 + c);
                sdata[c * COLPAD + padi(p)] =
                    make_uint4((uint32_t)__float2ll_rn(f.x),
                               (uint32_t)__float2ll_rn(f.y),
                               (uint32_t)__float2ll_rn(f.z),
                               (uint32_t)__float2ll_rn(f.w));
            }
        }
    }
    __syncthreads();                                    // tables + staging ready

    // Transform phase: group g = t>>8 owns column c0+g; named barriers only.
    int g    = t >> 8;
    int tloc = t & 255;
    uint4* smcol = sdata + g * COLPAD;
    uint4 x[8];
#pragma unroll
    for (int j = 0; j < 8; ++j) x[j] = smcol[padi(tloc + 256 * j)];
    dif2048(x, tloc, smcol, sTst, 1 + g);
#pragma unroll
    for (int j = 0; j < 8; ++j) {                       // fused scale, back to smem
        int r = 8 * tloc + j;
        unsigned k2 = __brev((unsigned)r) >> 21;
        unsigned e  = (unsigned)(c0 + g) * k2;          // < 2^22
        uint32_t w  = mmul(sT1[e >> 11], sT2[e & 2047]);
        scale4(x[j], w);
        smcol[padi(r)] = x[j];
    }
    __syncthreads();                                    // cross-group staging

    // Store phase: 32B-contiguous chunks (2 cols x 16B per row r).
    {
        int c = t & 1;
        int tp = t >> 1;
#pragma unroll
        for (int it = 0; it < 8; ++it) {
            int r = it * 256 + tp;
            g_buf[((size_t)r << 11) + c0 + c] = sdata[c * COLPAD + padi(r)];
        }
    }
}

// ---------------- pass B: 2 rows per CTA (2 CTAs/SM), f32 output ----------------
__global__ void __launch_bounds__(512, 2) ntt_pass_b(float* __restrict__ out,
                                                     const void* __restrict__ tw,
                                                     const void* __restrict__ ninv) {
    extern __shared__ uint4 smem_raw[];
    uint4*    sdata = smem_raw;                         // 2 x COLPAD
    uint32_t* sTst  = (uint32_t*)(smem_raw + 2 * COLPAD);   // 2048
    int t = threadIdx.x;
    int B = blockIdx.x;                                 // 0..1023
    int dt = probe_dtype(tw);
    build_tst(sTst, tw, dt, t, 512);

    // Group g transforms row B + 1024g; its k2 = 2*brev10(B) + g.
    int g    = t >> 8;
    int tloc = t & 255;
    int row  = B + (g << 10);
    uint4* smcol = sdata + g * COLPAD;
    const uint4* src = g_buf + ((size_t)row << 11);
    uint4 x[8];
#pragma unroll
    for (int j = 0; j < 8; ++j) x[j] = src[tloc + 256 * j];   // coalesced
    __syncthreads();                                    // sTst ready
    dif2048(x, tloc, smcol, sTst, 1 + g);
#pragma unroll
    for (int j = 0; j < 8; ++j) {                       // f32 bit patterns to smem
        int r = 8 * tloc + j;
        smcol[padi(r)] = make_uint4(__float_as_uint((float)x[j].x),
                                    __float_as_uint((float)x[j].y),
                                    __float_as_uint((float)x[j].z),
                                    __float_as_uint((float)x[j].w));
    }
    __syncthreads();                                    // cross-group staging

    // Store: out point (2K + c) + 2048*k1; c in {0,1} -> 32B sector chunks.
    {
        unsigned K = __brev((unsigned)B) >> 22;         // brev10(B)
        int c  = t & 1;                                 // group bit (brev1 = id)
        int tp = t >> 1;
#pragma unroll
        for (int it = 0; it < 8; ++it) {
            int jj = it * 256 + tp;
            unsigned k1 = __brev((unsigned)jj) >> 21;
            size_t o = (size_t)(2 * K + c) + ((size_t)k1 << 11);
            __stcs((uint4*)out + o, sdata[c * COLPAD + padi(jj)]);
        }
    }
}

extern "C" void kernel_launch(void* const* d_in, const int* in_sizes, int n_in,
                              void* d_out, int out_size) {
    // Identify inputs by element count: input = 2^24, twiddles = 2^21, n_inv = 1.
    const void* in = nullptr; const void* tw = nullptr; const void* ninv = nullptr;
    for (int i = 0; i < n_in; ++i) {
        if (in_sizes[i] == (int)(N_FULL * 4)) in = d_in[i];
        else if (in_sizes[i] == (int)N_HALF) tw = d_in[i];
        else ninv = d_in[i];
    }
    static bool attr_set = false;
    if (!attr_set) {
        cudaFuncSetAttribute(ntt_pass_a,
            cudaFuncAttributeMaxDynamicSharedMemorySize, SMEM_A_BYTES);
        cudaFuncSetAttribute(ntt_pass_b,
            cudaFuncAttributeMaxDynamicSharedMemorySize, SMEM_B_BYTES);
        attr_set = true;
    }
    ntt_pass_a<<<1024, 512, SMEM_A_BYTES>>>(in, tw, ninv);
    ntt_pass_b<<<1024, 512, SMEM_B_BYTES>>>((float*)d_out, tw, ninv);
}

// round 16
// speedup vs baseline: 1.2284x; 1.2284x over previous
#include <cuda_runtime.h>
#include <cstdint>

// ============================================================================
// Inverse NTT over F_P, P = 2013265921, N = 2^22, C = 4. Four-step 2048x2048.
// R16 = R14 (separate 5-block prep, global twiddle tables, stage-indexed
// butterfly table, Montgomery + lazy sub, 2 CTAs/SM) + pass-A input load
// lane remap from R15 (4 lanes cover one 64B chunk -> 8 lines/warp access).
// R15's prep-fold is REVERTED (per-CTA scattered table builds cost ~30us).
// ============================================================================

static constexpr uint32_t MOD    = 2013265921u;
static constexpr uint32_t N_FULL = 1u << 22;
static constexpr uint32_t N_HALF = 1u << 21;

static constexpr uint32_t calc_pinv() {
    uint32_t x = MOD;
    for (int i = 0; i < 5; ++i) x *= 2u - MOD * x;
    return x;
}
static constexpr uint32_t PINV_NEG = (uint32_t)(0u - calc_pinv());

static constexpr uint32_t calc_r2() {     // 2^64 mod P
    unsigned long long r = 1;
    for (int i = 0; i < 64; ++i) { r <<= 1; if (r >= MOD) r -= MOD; }
    return (uint32_t)r;
}
static constexpr uint32_t R2 = calc_r2();

#define DT_I32 0
#define DT_I64 1
#define DT_F32 2
#define DT_F64 3

static constexpr int COLPAD = 2305;       // padded uint4 stride per column
static constexpr int SMEM_A_BYTES = 2 * COLPAD * 16 + 3 * 2048 * 4;  // 98336
static constexpr int SMEM_B_BYTES = 2 * COLPAD * 16 + 2048 * 4;      // 81952

#define OFFH(H) (2048 - 2 * (H))          // stage-table base

__device__ uint32_t g_T1[2048];           // Montgomery omega^-{2048k} (full)
__device__ uint32_t g_T2[2048];           // Montgomery omega^-j * n_inv
__device__ uint32_t g_Tst[2048];          // stage-indexed butterfly twiddles
__device__ uint4    g_buf[N_FULL];        // 64 MB intermediate
__device__ int      g_dtype;

// Named barrier: 256 threads of group (id-1). Per-CTA resource.
#define NB(id) asm volatile("bar.sync %0, 256;" :: "r"(id) : "memory")

// ---------------- modular primitives (branch-free) ----------------
__device__ __forceinline__ uint32_t mmul(uint32_t a, uint32_t b) {
    // a < P (twiddle), b < 2P allowed: r < 1.938P, single min -> [0,P).
    unsigned long long t = (unsigned long long)a * b;
    uint32_t m = (uint32_t)t * PINV_NEG;
    uint32_t r = (uint32_t)((t + (unsigned long long)m * MOD) >> 32);
    return min(r, r - MOD);
}
__device__ __forceinline__ uint32_t addm(uint32_t a, uint32_t b) {
    uint32_t s = a + b; return min(s, s - MOD);
}
__device__ __forceinline__ uint32_t subm(uint32_t a, uint32_t b) {
    uint32_t d = a - b; return min(d, d + MOD);
}
__device__ __forceinline__ uint32_t subl(uint32_t a, uint32_t b) {
    return a - b + MOD;                   // lazy: < 2P, only feeds mmul
}

__device__ __forceinline__ void bfly(uint4& lo, uint4& hi, uint32_t tw) {
    uint32_t a, d;
    a = addm(lo.x, hi.x); d = subl(lo.x, hi.x); lo.x = a; hi.x = mmul(tw, d);
    a = addm(lo.y, hi.y); d = subl(lo.y, hi.y); lo.y = a; hi.y = mmul(tw, d);
    a = addm(lo.z, hi.z); d = subl(lo.z, hi.z); lo.z = a; hi.z = mmul(tw, d);
    a = addm(lo.w, hi.w); d = subl(lo.w, hi.w); lo.w = a; hi.w = mmul(tw, d);
}
__device__ __forceinline__ void bfly1(uint4& lo, uint4& hi) {   // twiddle == 1
    uint32_t a, d;
    a = addm(lo.x, hi.x); d = subm(lo.x, hi.x); lo.x = a; hi.x = d;
    a = addm(lo.y, hi.y); d = subm(lo.y, hi.y); lo.y = a; hi.y = d;
    a = addm(lo.z, hi.z); d = subm(lo.z, hi.z); lo.z = a; hi.z = d;
    a = addm(lo.w, hi.w); d = subm(lo.w, hi.w); lo.w = a; hi.w = d;
}
__device__ __forceinline__ void scale4(uint4& v, uint32_t tw) {
    v.x = mmul(tw, v.x); v.y = mmul(tw, v.y);
    v.z = mmul(tw, v.z); v.w = mmul(tw, v.w);
}

// Three consecutive DIF stages (halves 4S, 2S, S) with the stage-indexed
// table: twiddle for half H at lo-position p is ts[OFFH(H) + (p mod H)].
template <int S>
__device__ __forceinline__ void dif_group(uint4 x[8], int base,
                                          const uint32_t* ts) {
#pragma unroll
    for (int j = 0; j < 4; ++j) {                       // half = 4S
        int p = base + j * S;
        bfly(x[j], x[j + 4], ts[OFFH(4 * S) + (p & (4 * S - 1))]);
    }
#pragma unroll
    for (int k = 0; k < 4; ++k) {                       // half = 2S
        int j = (k & 1) + ((k & 2) << 1);
        int p = base + j * S;
        bfly(x[j], x[j + 2], ts[OFFH(2 * S) + (p & (2 * S - 1))]);
    }
#pragma unroll
    for (int j = 0; j < 8; j += 2) {                    // half = S
        int p = base + j * S;
        bfly(x[j], x[j + 1], ts[OFFH(S) + (p & (S - 1))]);
    }
}

__device__ __forceinline__ int padi(int i) { return i + (i >> 3); }

// In-place size-2048 DIF (validated choreography). Entry: x[j] = point
// (t+256j). Exit: x[j] = storage slot (8t+j); slot r holds output brev11(r).
__device__ __forceinline__ void dif2048(uint4 x[8], int t, uint4* sm,
                                        const uint32_t* ts, int bid) {
    dif_group<256>(x, t, ts);                           // halves 1024,512,256
#pragma unroll
    for (int j = 0; j < 8; ++j) sm[padi(t + 256 * j)] = x[j];
    NB(bid);
    int b1 = ((t >> 5) << 8) | (t & 31);
#pragma unroll
    for (int j = 0; j < 8; ++j) x[j] = sm[padi(b1 + 32 * j)];
    dif_group<32>(x, b1, ts);                           // halves 128,64,32
    NB(bid);
#pragma unroll
    for (int j = 0; j < 8; ++j) sm[padi(b1 + 32 * j)] = x[j];
    NB(bid);
    int b2 = ((t >> 2) << 5) | (t & 3);
#pragma unroll
    for (int j = 0; j < 8; ++j) x[j] = sm[padi(b2 + 4 * j)];
    dif_group<4>(x, b2, ts);                            // halves 16,8,4
    NB(bid);
#pragma unroll
    for (int j = 0; j < 8; ++j) sm[padi(b2 + 4 * j)] = x[j];
    NB(bid);
#pragma unroll
    for (int j = 0; j < 8; ++j) x[j] = sm[padi(8 * t + j)];
    uint32_t w512 = ts[OFFH(2) + 1];                    // = T1[512]; halves 2,1
    bfly1(x[0], x[2]); bfly(x[1], x[3], w512);
    bfly1(x[4], x[6]); bfly(x[5], x[7], w512);
    bfly1(x[0], x[1]); bfly1(x[2], x[3]);
    bfly1(x[4], x[5]); bfly1(x[6], x[7]);
}

// dtype probe (tw[0] == 1 in every encoding):
//   int64: w0=1,w1=0   int32: w0=1,w1!=0   f64: w0=0   f32: w0=0x3F800000
__device__ __forceinline__ int probe_dtype(const void* tw) {
    const uint32_t* w = (const uint32_t*)tw;
    if (w[0] == 1u) return (w[1] == 0u) ? DT_I64 : DT_I32;
    if (w[0] == 0u) return DT_F64;
    return DT_F32;
}
__device__ __forceinline__ uint32_t load_elem(const void* p, size_t i, int dt) {
    switch (dt) {
        case DT_I64: return (uint32_t)((const unsigned long long*)p)[i];
        case DT_F64: return (uint32_t)__double2ll_rn(((const double*)p)[i]);
        case DT_F32: return (uint32_t)__float2ll_rn(((const float*)p)[i]);
        default:     return ((const uint32_t*)p)[i];
    }
}

// ---------------- prep: twiddle tables (5 blocks x 1024) ----------------
__global__ void __launch_bounds__(1024) ntt_prep(const void* __restrict__ tw,
                                                 const void* __restrict__ ninv) {
    int dt = probe_dtype(tw);
    if (blockIdx.x == 0) {                              // full T1 (both halves)
        uint32_t v = mmul(load_elem(tw, (size_t)threadIdx.x << 11, dt), R2);
        g_T1[threadIdx.x] = v;
        g_T1[threadIdx.x + 1024] = MOD - v;             // omega^-{2^21} = -1
        if (threadIdx.x == 0) g_dtype = dt;
    } else if (blockIdx.x <= 2) {                       // T2[j] = tw[j]*ninv
        int j = (blockIdx.x - 1) * 1024 + threadIdx.x;  // 0..2047
        uint32_t nm = mmul(load_elem(ninv, 0, dt), R2);
        g_T2[j] = mmul(mmul(load_elem(tw, j, dt), R2), nm);
    } else {                                            // stage-indexed table
        int E = (blockIdx.x - 3) * 1024 + threadIdx.x;  // 0..2047
        if (E < 2046) {                                 // max used idx = 2045
            unsigned u = 2048u - (unsigned)E;           // u in (H, 2H]
            int lg = 31 - __clz(u - 1);                 // log2 H
            int i  = (2 << lg) - (int)u;                // i < H
            size_t expi = (size_t)i << (21 - lg);       // (i*1024/H) << 11
            g_Tst[E] = mmul(load_elem(tw, expi, dt), R2);
        }
    }
}

// ---------------- pass A: 2 columns per CTA (2 CTAs/SM) ----------------
__global__ void __launch_bounds__(512, 2) ntt_pass_a(const void* __restrict__ in) {
    extern __shared__ uint4 smem_raw[];
    uint4*    sdata = smem_raw;                         // 2 x COLPAD
    uint32_t* sTst  = (uint32_t*)(smem_raw + 2 * COLPAD);   // 2048
    uint32_t* sT1   = sTst + 2048;                      // 2048 (full, scale)
    uint32_t* sT2   = sT1 + 2048;                       // 2048 (scale)
    int t  = threadIdx.x;
    int c0 = blockIdx.x * 2;
    int dt = g_dtype;
    for (int i = t; i < 2048; i += 512) {
        sTst[i] = g_Tst[i]; sT1[i] = g_T1[i]; sT2[i] = g_T2[i];
    }

    // Load phase. int64/f64: lanes (q = 16B chunk-of-64B, rows) -> every
    // warp access covers 8 full 64B chunks = 8 lines (64B/wavefront).
    if (dt == DT_I64 || dt == DT_F64) {
        int q  = t & 3;                                 // 16B chunk in 64B row-pair
        int c  = q >> 1;                                // column
        int h  = q & 1;                                 // uint4 half (.xy/.zw)
        int tp = t >> 2;                                // 128 row slots
        const char* base = (const char*)in;
#pragma unroll
        for (int it = 0; it < 16; ++it) {
            int p = it * 128 + tp;
            const char* chunk = base + ((size_t)p * 2048 + c0) * 32 + q * 16;
            uint2 w;
            if (dt == DT_I64) {
                ulonglong2 v = __ldcs((const ulonglong2*)chunk);
                w = make_uint2((uint32_t)v.x, (uint32_t)v.y);
            } else {
                double2 v = __ldcs((const double2*)chunk);
                w = make_uint2((uint32_t)__double2ll_rn(v.x),
                               (uint32_t)__double2ll_rn(v.y));
            }
            *((uint2*)(sdata + c * COLPAD + padi(p)) + h) = w;
        }
    } else {                                            // 16B/point dtypes
        int c = t & 1;
        int tp = t >> 1;
        if (dt == DT_I32) {
#pragma unroll
            for (int it = 0; it < 8; ++it) {
                int p = it * 256 + tp;
                sdata[c * COLPAD + padi(p)] =
                    __ldcs((const uint4*)in + (size_t)p * 2048 + c0 + c);
            }
        } else {                                        // DT_F32
#pragma unroll
            for (int it = 0; it < 8; ++it) {
                int p = it * 256 + tp;
                float4 f = __ldcs((const float4*)in + (size_t)p * 2048 + c0 + c);
                sdata[c * COLPAD + padi(p)] =
                    make_uint4((uint32_t)__float2ll_rn(f.x),
                               (uint32_t)__float2ll_rn(f.y),
                               (uint32_t)__float2ll_rn(f.z),
                               (uint32_t)__float2ll_rn(f.w));
            }
        }
    }
    __syncthreads();                                    // cross-group staging

    // Transform phase: group g = t>>8 owns column c0+g; named barriers only.
    int g    = t >> 8;
    int tloc = t & 255;
    uint4* smcol = sdata + g * COLPAD;
    uint4 x[8];
#pragma unroll
    for (int j = 0; j < 8; ++j) x[j] = smcol[padi(tloc + 256 * j)];
    dif2048(x, tloc, smcol, sTst, 1 + g);
#pragma unroll
    for (int j = 0; j < 8; ++j) {                       // fused scale, back to smem
        int r = 8 * tloc + j;
        unsigned k2 = __brev((unsigned)r) >> 21;
        unsigned e  = (unsigned)(c0 + g) * k2;          // < 2^22
        uint32_t w  = mmul(sT1[e >> 11], sT2[e & 2047]);
        scale4(x[j], w);
        smcol[padi(r)] = x[j];
    }
    __syncthreads();                                    // cross-group staging

    // Store phase: 32B-contiguous chunks (2 cols x 16B per row r).
    {
        int c = t & 1;
        int tp = t >> 1;
#pragma unroll
        for (int it = 0; it < 8; ++it) {
            int r = it * 256 + tp;
            g_buf[((size_t)r << 11) + c0 + c] = sdata[c * COLPAD + padi(r)];
        }
    }
}

// ---------------- pass B: 2 rows per CTA (2 CTAs/SM), f32 output ----------------
__global__ void __launch_bounds__(512, 2) ntt_pass_b(float* __restrict__ out) {
    extern __shared__ uint4 smem_raw[];
    uint4*    sdata = smem_raw;                         // 2 x COLPAD
    uint32_t* sTst  = (uint32_t*)(smem_raw + 2 * COLPAD);   // 2048
    int t = threadIdx.x;
    int B = blockIdx.x;                                 // 0..1023
    for (int i = t; i < 2048; i += 512) sTst[i] = g_Tst[i];

    // Group g transforms row B + 1024g; its k2 = 2*brev10(B) + g.
    int g    = t >> 8;
    int tloc = t & 255;
    int row  = B + (g << 10);
    uint4* smcol = sdata + g * COLPAD;
    const uint4* src = g_buf + ((size_t)row << 11);
    uint4 x[8];
#pragma unroll
    for (int j = 0; j < 8; ++j) x[j] = src[tloc + 256 * j];   // coalesced
    __syncthreads();                                    // sTst ready
    dif2048(x, tloc, smcol, sTst, 1 + g);
#pragma unroll
    for (int j = 0; j < 8; ++j) {                       // f32 bit patterns to smem
        int r = 8 * tloc + j;
        smcol[padi(r)] = make_uint4(__float_as_uint((float)x[j].x),
                                    __float_as_uint((float)x[j].y),
                                    __float_as_uint((float)x[j].z),
                                    __float_as_uint((float)x[j].w));
    }
    __syncthreads();                                    // cross-group staging

    // Store: out point (2K + c) + 2048*k1; c in {0,1} -> 32B sector chunks.
    {
        unsigned K = __brev((unsigned)B) >> 22;         // brev10(B)
        int c  = t & 1;                                 // group bit (brev1 = id)
        int tp = t >> 1;
#pragma unroll
        for (int it = 0; it < 8; ++it) {
            int jj = it * 256 + tp;
            unsigned k1 = __brev((unsigned)jj) >> 21;
            size_t o = (size_t)(2 * K + c) + ((size_t)k1 << 11);
            __stcs((uint4*)out + o, sdata[c * COLPAD + padi(jj)]);
        }
    }
}

extern "C" void kernel_launch(void* const* d_in, const int* in_sizes, int n_in,
                              void* d_out, int out_size) {
    // Identify inputs by element count: input = 2^24, twiddles = 2^21, n_inv = 1.
    const void* in = nullptr; const void* tw = nullptr; const void* ninv = nullptr;
    for (int i = 0; i < n_in; ++i) {
        if (in_sizes[i] == (int)(N_FULL * 4)) in = d_in[i];
        else if (in_sizes[i] == (int)N_HALF) tw = d_in[i];
        else ninv = d_in[i];
    }
    static bool attr_set = false;
    if (!attr_set) {
        cudaFuncSetAttribute(ntt_pass_a,
            cudaFuncAttributeMaxDynamicSharedMemorySize, SMEM_A_BYTES);
        cudaFuncSetAttribute(ntt_pass_b,
            cudaFuncAttributeMaxDynamicSharedMemorySize, SMEM_B_BYTES);
        attr_set = true;
    }
    ntt_prep  <<<   5, 1024>>>(tw, ninv);
    ntt_pass_a<<<1024,  512, SMEM_A_BYTES>>>(in);
    ntt_pass_b<<<1024,  512, SMEM_B_BYTES>>>((float*)d_out);
}

// round 17
// speedup vs baseline: 1.2476x; 1.0156x over previous
#include <cuda_runtime.h>
#include <cstdint>

// ============================================================================
// Inverse NTT over F_P, P = 2013265921, N = 2^22, C = 4. Four-step 2048x2048.
// R17: 16-points-per-thread transform over uint2 channel-pairs ("planes").
// 11 DIF stages grouped 4+4+3 -> only 2 smem exchanges + 2 named barriers
// (vs 3 exchanges / 5 barriers with 8xuint4). CTA = 512 thr = 4 groups of 128:
// pass A: 2 n1-columns x 2 planes; pass B: 2 rows x 2 planes.
// Montgomery + lazy sub, stage-indexed twiddle table, 2 CTAs/SM.
// ============================================================================

static constexpr uint32_t MOD    = 2013265921u;
static constexpr uint32_t N_FULL = 1u << 22;
static constexpr uint32_t N_HALF = 1u << 21;

static constexpr uint32_t calc_pinv() {
    uint32_t x = MOD;
    for (int i = 0; i < 5; ++i) x *= 2u - MOD * x;
    return x;
}
static constexpr uint32_t PINV_NEG = (uint32_t)(0u - calc_pinv());

static constexpr uint32_t calc_r2() {     // 2^64 mod P
    unsigned long long r = 1;
    for (int i = 0; i < 64; ++i) { r <<= 1; if (r >= MOD) r -= MOD; }
    return (uint32_t)r;
}
static constexpr uint32_t R2 = calc_r2();

#define DT_I32 0
#define DT_I64 1
#define DT_F32 2
#define DT_F64 3

// Plane region: 2048 uint2 with pad16(i)=i+(i>>4) (max 2174) -> stride 2180.
// 2*2180 banks per region = 4360 = 8 mod 32: regions land 8 banks apart.
static constexpr int G2PAD = 2180;        // uint2 stride per plane region
static constexpr int SMEM_A_BYTES = 4 * G2PAD * 8 + 3 * 2048 * 4;  // 94336
static constexpr int SMEM_B_BYTES = 4 * G2PAD * 8 + 2048 * 4;      // 77952

#define OFFH(H) (2048 - 2 * (H))          // stage-table base
#define NB128(id) asm volatile("bar.sync %0, 128;" :: "r"(id) : "memory")

__device__ uint32_t g_T1[2048];           // Montgomery omega^-{2048k}
__device__ uint32_t g_T2[2048];           // Montgomery omega^-j * n_inv
__device__ uint32_t g_Tst[2048];          // stage-indexed butterfly twiddles
__device__ uint4    g_buf[N_FULL];        // 64 MB intermediate
__device__ int      g_dtype;

// ---------------- modular primitives (branch-free) ----------------
__device__ __forceinline__ uint32_t mmul(uint32_t a, uint32_t b) {
    // a < P (twiddle), b < 2P allowed: r < 1.938P, single min -> [0,P).
    unsigned long long t = (unsigned long long)a * b;
    uint32_t m = (uint32_t)t * PINV_NEG;
    uint32_t r = (uint32_t)((t + (unsigned long long)m * MOD) >> 32);
    return min(r, r - MOD);
}
__device__ __forceinline__ uint32_t addm(uint32_t a, uint32_t b) {
    uint32_t s = a + b; return min(s, s - MOD);
}
__device__ __forceinline__ uint32_t subm(uint32_t a, uint32_t b) {
    uint32_t d = a - b; return min(d, d + MOD);
}
__device__ __forceinline__ uint32_t subl(uint32_t a, uint32_t b) {
    return a - b + MOD;                   // lazy: < 2P, only feeds mmul
}

__device__ __forceinline__ void bfly2(uint2& lo, uint2& hi, uint32_t tw) {
    uint32_t a, d;
    a = addm(lo.x, hi.x); d = subl(lo.x, hi.x); lo.x = a; hi.x = mmul(tw, d);
    a = addm(lo.y, hi.y); d = subl(lo.y, hi.y); lo.y = a; hi.y = mmul(tw, d);
}
__device__ __forceinline__ void bfly2_1(uint2& lo, uint2& hi) {  // twiddle == 1
    uint32_t a, d;
    a = addm(lo.x, hi.x); d = subm(lo.x, hi.x); lo.x = a; hi.x = d;
    a = addm(lo.y, hi.y); d = subm(lo.y, hi.y); lo.y = a; hi.y = d;
}

__device__ __forceinline__ int pad16(int i) { return i + (i >> 4); }

// Four consecutive DIF stages (halves 8S,4S,2S,S) on 16 register points at
// p_j = base + j*S. Twiddle for half H at lo-position p: ts[OFFH(H)+(p&(H-1))].
template <int S>
__device__ __forceinline__ void dif_g4(uint2 x[16], int base,
                                       const uint32_t* ts) {
#pragma unroll
    for (int j = 0; j < 8; ++j) {                       // half = 8S: (j, j+8)
        int p = base + j * S;
        bfly2(x[j], x[j + 8], ts[OFFH(8 * S) + (p & (8 * S - 1))]);
    }
#pragma unroll
    for (int k = 0; k < 8; ++k) {                       // half = 4S: (j, j+4)
        int j = (k & 3) | ((k & 4) << 1);               // {0..3, 8..11}
        int p = base + j * S;
        bfly2(x[j], x[j + 4], ts[OFFH(4 * S) + (p & (4 * S - 1))]);
    }
#pragma unroll
    for (int k = 0; k < 8; ++k) {                       // half = 2S: (j, j+2)
        int j = (k & 1) | ((k & 6) << 1);               // {0,1,4,5,8,9,12,13}
        int p = base + j * S;
        bfly2(x[j], x[j + 2], ts[OFFH(2 * S) + (p & (2 * S - 1))]);
    }
#pragma unroll
    for (int k = 0; k < 8; ++k) {                       // half = S: (j, j+1)
        int j = 2 * k;
        int p = base + j * S;
        bfly2(x[j], x[j + 1], ts[OFFH(S) + (p & (S - 1))]);
    }
}

// Final three stages (halves 4, 2, 1) on 16 consecutive points base..base+15.
__device__ __forceinline__ void dif_g3f(uint2 x[16], int base,
                                        const uint32_t* ts) {
#pragma unroll
    for (int k = 0; k < 8; ++k) {                       // half = 4
        int j = (k & 3) | ((k & 4) << 1);
        int p = base + j;
        bfly2(x[j], x[j + 4], ts[OFFH(4) + (p & 3)]);
    }
#pragma unroll
    for (int k = 0; k < 8; ++k) {                       // half = 2
        int j = (k & 1) | ((k & 6) << 1);
        int p = base + j;
        bfly2(x[j], x[j + 2], ts[OFFH(2) + (p & 1)]);
    }
#pragma unroll
    for (int k = 0; k < 8; ++k)                         // half = 1
        bfly2_1(x[2 * k], x[2 * k + 1]);
}

// In-place size-2048 DIF, 16 points/thread (tl in 0..127), plane data uint2.
// Entry: x[j] = point(tl + 128j). Exit: x[j] = storage slot (16tl + j);
// slot r holds output point brev11(r). 2 exchanges, 2 named barriers.
__device__ __forceinline__ void dif2048v2(uint2 x[16], int tl, uint2* sm,
                                          const uint32_t* ts, int bid) {
    dif_g4<128>(x, tl, ts);                             // halves 1024..128
#pragma unroll
    for (int j = 0; j < 16; ++j) sm[pad16(tl + 128 * j)] = x[j];
    NB128(bid);
    int q1 = ((tl >> 3) << 7) | (tl & 7);
#pragma unroll
    for (int j = 0; j < 16; ++j) x[j] = sm[pad16(q1 + 8 * j)];
    dif_g4<8>(x, q1, ts);                               // halves 64..8
#pragma unroll
    for (int j = 0; j < 16; ++j) sm[pad16(q1 + 8 * j)] = x[j];   // own slots
    NB128(bid);
#pragma unroll
    for (int j = 0; j < 16; ++j) x[j] = sm[pad16(16 * tl + j)];
    dif_g3f(x, 16 * tl, ts);                            // halves 4,2,1
}

// dtype probe (tw[0] == 1 in every encoding):
//   int64: w0=1,w1=0   int32: w0=1,w1!=0   f64: w0=0   f32: w0=0x3F800000
__device__ __forceinline__ int probe_dtype(const void* tw) {
    const uint32_t* w = (const uint32_t*)tw;
    if (w[0] == 1u) return (w[1] == 0u) ? DT_I64 : DT_I32;
    if (w[0] == 0u) return DT_F64;
    return DT_F32;
}
__device__ __forceinline__ uint32_t load_elem(const void* p, size_t i, int dt) {
    switch (dt) {
        case DT_I64: return (uint32_t)((const unsigned long long*)p)[i];
        case DT_F64: return (uint32_t)__double2ll_rn(((const double*)p)[i]);
        case DT_F32: return (uint32_t)__float2ll_rn(((const float*)p)[i]);
        default:     return ((const uint32_t*)p)[i];
    }
}

// ---------------- prep: twiddle tables (5 blocks x 1024) ----------------
__global__ void __launch_bounds__(1024) ntt_prep(const void* __restrict__ tw,
                                                 const void* __restrict__ ninv) {
    int dt = probe_dtype(tw);
    if (blockIdx.x == 0) {                              // full T1 (both halves)
        uint32_t v = mmul(load_elem(tw, (size_t)threadIdx.x << 11, dt), R2);
        g_T1[threadIdx.x] = v;
        g_T1[threadIdx.x + 1024] = MOD - v;             // omega^-{2^21} = -1
        if (threadIdx.x == 0) g_dtype = dt;
    } else if (blockIdx.x <= 2) {                       // T2[j] = tw[j]*ninv
        int j = (blockIdx.x - 1) * 1024 + threadIdx.x;  // 0..2047
        uint32_t nm = mmul(load_elem(ninv, 0, dt), R2);
        g_T2[j] = mmul(mmul(load_elem(tw, j, dt), R2), nm);
    } else {                                            // stage-indexed table
        int E = (blockIdx.x - 3) * 1024 + threadIdx.x;  // 0..2047
        if (E < 2046) {
            unsigned u = 2048u - (unsigned)E;           // u in (H, 2H]
            int lg = 31 - __clz(u - 1);                 // log2 H
            int i  = (2 << lg) - (int)u;                // i < H
            size_t expi = (size_t)i << (21 - lg);       // (i*1024/H) << 11
            g_Tst[E] = mmul(load_elem(tw, expi, dt), R2);
        }
    }
}

// ---------------- pass A: 2 columns x 2 planes per CTA ----------------
__global__ void __launch_bounds__(512, 2) ntt_pass_a(const void* __restrict__ in) {
    extern __shared__ uint2 smem2[];
    uint2*    sdata = smem2;                            // 4 x G2PAD
    uint32_t* sTst  = (uint32_t*)(smem2 + 4 * G2PAD);   // 2048
    uint32_t* sT1   = sTst + 2048;
    uint32_t* sT2   = sT1 + 2048;
    int t  = threadIdx.x;
    int c0 = blockIdx.x * 2;
    int dt = g_dtype;
    for (int i = t; i < 2048; i += 512) {
        sTst[i] = g_Tst[i]; sT1[i] = g_T1[i]; sT2[i] = g_T2[i];
    }

    // Load phase: q = t&3 selects region (n1loc = q>>1, plane = q&1); lanes
    // 0-3 cover one row-pair's 64B (i64) / 32B (i32) contiguously.
    {
        int q  = t & 3;
        int tp = t >> 2;
        uint2* reg = sdata + q * G2PAD;
        if (dt == DT_I64) {
            const char* base = (const char*)in;
#pragma unroll
            for (int it = 0; it < 16; ++it) {
                int p = it * 128 + tp;
                ulonglong2 v = __ldcs((const ulonglong2*)
                    (base + ((size_t)p * 2048 + c0) * 32 + q * 16));
                reg[pad16(p)] = make_uint2((uint32_t)v.x, (uint32_t)v.y);
            }
        } else if (dt == DT_F64) {
            const char* base = (const char*)in;
#pragma unroll
            for (int it = 0; it < 16; ++it) {
                int p = it * 128 + tp;
                double2 v = __ldcs((const double2*)
                    (base + ((size_t)p * 2048 + c0) * 32 + q * 16));
                reg[pad16(p)] = make_uint2((uint32_t)__double2ll_rn(v.x),
                                           (uint32_t)__double2ll_rn(v.y));
            }
        } else if (dt == DT_I32) {
#pragma unroll
            for (int it = 0; it < 16; ++it) {
                int p = it * 128 + tp;
                reg[pad16(p)] = __ldcs((const uint2*)in
                                       + ((size_t)p * 2048 + c0) * 2 + q);
            }
        } else {                                        // DT_F32
#pragma unroll
            for (int it = 0; it < 16; ++it) {
                int p = it * 128 + tp;
                float2 f = __ldcs((const float2*)in
                                  + ((size_t)p * 2048 + c0) * 2 + q);
                reg[pad16(p)] = make_uint2((uint32_t)__float2ll_rn(f.x),
                                           (uint32_t)__float2ll_rn(f.y));
            }
        }
    }
    __syncthreads();                                    // tables + staging

    // Transform: group g = t>>7 owns (n1 = c0 + (g>>1), plane = g&1).
    int g    = t >> 7;
    int tl   = t & 127;
    int n1   = c0 + (g >> 1);
    uint2* reg = sdata + g * G2PAD;
    uint2 x[16];
#pragma unroll
    for (int j = 0; j < 16; ++j) x[j] = reg[pad16(tl + 128 * j)];
    dif2048v2(x, tl, reg, sTst, 1 + g);
#pragma unroll
    for (int j = 0; j < 16; ++j) {                      // fused scale, restage
        int r = 16 * tl + j;
        unsigned k2 = __brev((unsigned)r) >> 21;
        unsigned e  = (unsigned)n1 * k2;                // < 2^22
        uint32_t w  = mmul(sT1[e >> 11], sT2[e & 2047]);
        x[j].x = mmul(w, x[j].x);
        x[j].y = mmul(w, x[j].y);
        reg[pad16(r)] = x[j];
    }
    __syncthreads();                                    // cross-group staging

    // Store: combine planes -> uint4; 32B-contiguous (2 cols x 16B per row).
    {
        int c  = t & 1;                                 // n1-local
        int tp = t >> 1;
        const uint2* r01 = sdata + (c * 2 + 0) * G2PAD; // plane 0 (ch01)
        const uint2* r23 = sdata + (c * 2 + 1) * G2PAD; // plane 1 (ch23)
#pragma unroll
        for (int it = 0; it < 8; ++it) {
            int r = it * 256 + tp;
            uint2 lo = r01[pad16(r)], hi = r23[pad16(r)];
            g_buf[((size_t)r << 11) + c0 + c] = make_uint4(lo.x, lo.y,
                                                           hi.x, hi.y);
        }
    }
}

// ---------------- pass B: 2 rows x 2 planes per CTA, f32 output ----------------
__global__ void __launch_bounds__(512, 2) ntt_pass_b(float* __restrict__ out) {
    extern __shared__ uint2 smem2[];
    uint2*    sdata = smem2;                            // 4 x G2PAD
    uint32_t* sTst  = (uint32_t*)(smem2 + 4 * G2PAD);   // 2048
    int t = threadIdx.x;
    int B = blockIdx.x;                                 // 0..1023
    for (int i = t; i < 2048; i += 512) sTst[i] = g_Tst[i];

    // Group g: row = B + (g>>1)*1024, plane = g&1. Direct uint2 loads
    // (plane halves of the row's uint4s; partner group covers the other half).
    int g    = t >> 7;
    int tl   = t & 127;
    int row  = B + ((g >> 1) << 10);
    int pl   = g & 1;
    uint2* reg = sdata + g * G2PAD;
    const uint2* src = (const uint2*)(g_buf + ((size_t)row << 11)) + pl;
    uint2 x[16];
#pragma unroll
    for (int j = 0; j < 16; ++j) x[j] = src[2 * (tl + 128 * j)];
    __syncthreads();                                    // sTst ready
    dif2048v2(x, tl, reg, sTst, 1 + g);
#pragma unroll
    for (int j = 0; j < 16; ++j) {                      // f32 bits, restage
        int r = 16 * tl + j;
        reg[pad16(r)] = make_uint2(__float_as_uint((float)x[j].x),
                                   __float_as_uint((float)x[j].y));
    }
    __syncthreads();                                    // cross-group staging

    // Store: out point (2K + c) + 2048*k1 as uint4 from the two planes.
    {
        unsigned K = __brev((unsigned)B) >> 22;         // brev10(B)
        int c  = t & 1;                                 // row-local
        int tp = t >> 1;
        const uint2* r01 = sdata + (c * 2 + 0) * G2PAD;
        const uint2* r23 = sdata + (c * 2 + 1) * G2PAD;
#pragma unroll
        for (int it = 0; it < 8; ++it) {
            int jj = it * 256 + tp;
            unsigned k1 = __brev((unsigned)jj) >> 21;
            uint2 lo = r01[pad16(jj)], hi = r23[pad16(jj)];
            size_t o = (size_t)(2 * K + c) + ((size_t)k1 << 11);
            __stcs((uint4*)out + o, make_uint4(lo.x, lo.y, hi.x, hi.y));
        }
    }
}

extern "C" void kernel_launch(void* const* d_in, const int* in_sizes, int n_in,
                              void* d_out, int out_size) {
    // Identify inputs by element count: input = 2^24, twiddles = 2^21, n_inv = 1.
    const void* in = nullptr; const void* tw = nullptr; const void* ninv = nullptr;
    for (int i = 0; i < n_in; ++i) {
        if (in_sizes[i] == (int)(N_FULL * 4)) in = d_in[i];
        else if (in_sizes[i] == (int)N_HALF) tw = d_in[i];
        else ninv = d_in[i];
    }
    static bool attr_set = false;
    if (!attr_set) {
        cudaFuncSetAttribute(ntt_pass_a,
            cudaFuncAttributeMaxDynamicSharedMemorySize, SMEM_A_BYTES);
        cudaFuncSetAttribute(ntt_pass_b,
            cudaFuncAttributeMaxDynamicSharedMemorySize, SMEM_B_BYTES);
        attr_set = true;
    }
    ntt_prep  <<<   5, 1024>>>(tw, ninv);
    ntt_pass_a<<<1024,  512, SMEM_A_BYTES>>>(in);
    ntt_pass_b<<<1024,  512, SMEM_B_BYTES>>>((float*)d_out);
}